// round 14
// baseline (speedup 1.0000x reference)
#include <cuda_runtime.h>
#include <cuda_bf16.h>
#include <cstdint>

#define BATCH 8
#define CH    512
#define NPIX  4096
#define EPS   1e-6f

// ---------------------------------------------------------------------------
// Scratch (__device__ globals: allocation-free per harness rules)
// ---------------------------------------------------------------------------
__device__ __nv_bfloat16 g_ht[BATCH * NPIX * CH];   // h^T [b][n][c]
__device__ __nv_bfloat16 g_qt[BATCH * NPIX * CH];   // q^T [b][n][d] (unscaled)
__device__ __nv_bfloat16 g_kt[BATCH * NPIX * CH];   // k^T [b][n][d]
__device__ __nv_bfloat16 g_v [BATCH * CH * NPIX];   // v   [b][d][n]
__device__ __nv_bfloat16 g_ot[BATCH * NPIX * CH];   // o^T [b][n][c]
__device__ __nv_bfloat16 g_S [134217728];           // [b][i][j] exp(logits)
__device__ float         g_rowsum[BATCH * NPIX];    // softmax denominators
__device__ __nv_bfloat16 g_wq[CH * CH], g_wk[CH * CH], g_wv[CH * CH], g_wp[CH * CH];

// ---------------------------------------------------------------------------
// PTX helpers (base-arch features only: PTX target is sm_103 w/o 'a' suffix)
// ---------------------------------------------------------------------------
__device__ __forceinline__ uint32_t smem_u32(const void* p) {
    uint32_t a;
    asm("{ .reg .u64 t; cvta.to.shared.u64 t, %1; cvt.u32.u64 %0, t; }"
        : "=r"(a) : "l"(p));
    return a;
}
__device__ __forceinline__ void cp_async16(uint32_t saddr, const void* gptr) {
    asm volatile("cp.async.cg.shared.global [%0], [%1], 16;\n"
                 :: "r"(saddr), "l"(gptr));
}
#define CP_COMMIT() asm volatile("cp.async.commit_group;\n" ::: "memory")
#define CP_WAIT(N)  asm volatile("cp.async.wait_group %0;\n" :: "n"(N) : "memory")

__device__ __forceinline__ void ldsm4(uint32_t* r, uint32_t addr) {
    asm volatile("ldmatrix.sync.aligned.m8n8.x4.shared.b16 {%0,%1,%2,%3}, [%4];"
                 : "=r"(r[0]), "=r"(r[1]), "=r"(r[2]), "=r"(r[3]) : "r"(addr));
}
__device__ __forceinline__ void mma16816(float* c, const uint32_t* a,
                                         uint32_t b0, uint32_t b1) {
    asm volatile("mma.sync.aligned.m16n8k16.row.col.f32.bf16.bf16.f32 "
                 "{%0,%1,%2,%3}, {%4,%5,%6,%7}, {%8,%9}, {%0,%1,%2,%3};"
                 : "+f"(c[0]), "+f"(c[1]), "+f"(c[2]), "+f"(c[3])
                 : "r"(a[0]), "r"(a[1]), "r"(a[2]), "r"(a[3]), "r"(b0), "r"(b1));
}

// ---------------------------------------------------------------------------
// GroupNorm -> bf16 h^T[b][n][c]; ALSO folds in weight fp32->bf16 conversion
// (one float4 per thread: 256 blocks x 1024 thr == 262144 units) and
// g_rowsum zeroing, eliminating the separate wconv launch.
// ---------------------------------------------------------------------------
__global__ __launch_bounds__(1024) void gn_kernel(const float* __restrict__ x,
                                                  const float* __restrict__ w,
                                                  const float* __restrict__ bgn,
                                                  const float* __restrict__ qw,
                                                  const float* __restrict__ kw,
                                                  const float* __restrict__ vw,
                                                  const float* __restrict__ pw) {
    int bg = blockIdx.x;                       // b*32 + g
    int tid = threadIdx.x;

    // ---- folded weight conversion + rowsum zero (independent work) ----
    {
        int i4 = bg * 1024 + tid;              // 0..262143 float4 units
        if (i4 < BATCH * NPIX) g_rowsum[i4] = 0.f;
        const float* src = (i4 < 65536) ? qw : (i4 < 131072) ? kw
                          : (i4 < 196608) ? vw : pw;
        __nv_bfloat16* dst = (i4 < 65536) ? g_wq : (i4 < 131072) ? g_wk
                            : (i4 < 196608) ? g_wv : g_wp;
        int off = i4 & 65535;
        float4 vv = ((const float4*)src)[off];
        __nv_bfloat162 lo = __floats2bfloat162_rn(vv.x, vv.y);
        __nv_bfloat162 hi = __floats2bfloat162_rn(vv.z, vv.w);
        uint2 u; u.x = *(uint32_t*)&lo; u.y = *(uint32_t*)&hi;
        ((uint2*)dst)[off] = u;
    }

    // ---- GroupNorm proper ----
    size_t base = (size_t)bg * (16 * NPIX);
    const float4* x4 = (const float4*)(x + base);

    float s = 0.f, ss = 0.f;
    #pragma unroll
    for (int t = 0; t < 16; t++) {
        float4 v = x4[tid + t * 1024];
        s  += v.x + v.y + v.z + v.w;
        ss += v.x * v.x + v.y * v.y + v.z * v.z + v.w * v.w;
    }
    __shared__ float rs[32], rss[32];
    __shared__ float sc_s[16], off_s[16];
    #pragma unroll
    for (int o = 16; o; o >>= 1) {
        s  += __shfl_xor_sync(0xffffffffu, s, o);
        ss += __shfl_xor_sync(0xffffffffu, ss, o);
    }
    if ((tid & 31) == 0) { rs[tid >> 5] = s; rss[tid >> 5] = ss; }
    __syncthreads();
    if (tid < 32) {
        s = rs[tid]; ss = rss[tid];
        #pragma unroll
        for (int o = 16; o; o >>= 1) {
            s  += __shfl_xor_sync(0xffffffffu, s, o);
            ss += __shfl_xor_sync(0xffffffffu, ss, o);
        }
        if (tid == 0) {
            float mean = s * (1.f / 65536.f);
            float var  = ss * (1.f / 65536.f) - mean * mean;
            rs[0] = mean; rss[0] = rsqrtf(var + EPS);
        }
    }
    __syncthreads();
    int b = bg >> 5, g = bg & 31, c0 = g * 16;
    if (tid < 16) {
        float mean = rs[0], inv = rss[0];
        float scv = w[c0 + tid] * inv;
        sc_s[tid]  = scv;
        off_s[tid] = bgn[c0 + tid] - mean * scv;
    }
    __syncthreads();

    #pragma unroll
    for (int nb = 0; nb < 4; nb++) {
        int n = nb * 1024 + tid;
        __nv_bfloat16 hv[16];
        #pragma unroll
        for (int cc = 0; cc < 16; cc++) {
            float xv = x[base + (size_t)cc * NPIX + n];
            hv[cc] = __float2bfloat16(xv * sc_s[cc] + off_s[cc]);
        }
        uint4* dst = (uint4*)(g_ht + ((size_t)b * NPIX + n) * CH + c0);
        uint4* src = (uint4*)hv;
        dst[0] = src[0];
        dst[1] = src[1];
    }
}

// ---------------------------------------------------------------------------
// Merged q/k/v conv GEMM, one launch. grid (4, 32, 24):
//   z in [0,8)   : q^T[n][d] = h^T . Wq^T + qb   (m0 from y, n0 from x, bias[col])
//   z in [8,16)  : k^T[n][d] = h^T . Wk^T + kb   (same shape)
//   z in [16,24) : v[d][n]   = Wv . h^T^T + vb   (m0 from x, n0 from y, bias[row])
// Same mainloop as tc_gemm, K=512 fixed (8 chunks). All selection is uniform.
// ---------------------------------------------------------------------------
__global__ void __launch_bounds__(256, 2) qkv_gemm(
    const float* __restrict__ q_b, const float* __restrict__ k_b,
    const float* __restrict__ v_b)
{
    extern __shared__ char dsm[];
    uint32_t sb = smem_u32(dsm);
    const uint32_t STG = 32768;
    int tid = threadIdx.x, wid = tid >> 5, lane = tid & 31;
    int wm = wid >> 2, wn = wid & 3;

    const unsigned long long sNC = (unsigned long long)NPIX * CH;

    int z = blockIdx.z;
    int b = z & 7;
    bool is_v = (z >= 16);
    int m0, n0, ldC;
    const __nv_bfloat16 *Ab, *Bb;
    __nv_bfloat16* Cb;
    const float* bias;
    if (!is_v) {
        bool is_q = (z < 8);
        m0 = blockIdx.y * 128;                 // n tiles (4096)
        n0 = blockIdx.x * 128;                 // d tiles (512)
        Ab = g_ht + (size_t)b * sNC + (size_t)m0 * CH;
        Bb = (is_q ? g_wq : g_wk) + (size_t)n0 * CH;
        Cb = (is_q ? g_qt : g_kt) + (size_t)b * sNC;
        bias = is_q ? q_b : k_b;
        ldC = CH;
    } else {
        m0 = blockIdx.x * 128;                 // d tiles (512)
        n0 = blockIdx.y * 128;                 // n tiles (4096)
        Ab = g_wv + (size_t)m0 * CH;
        Bb = g_ht + (size_t)b * sNC + (size_t)n0 * CH;
        Cb = g_v + (size_t)b * sNC;
        bias = v_b;
        ldC = NPIX;
    }

    int a_row = wm * 64 + (lane & 7) + ((lane >> 3) & 1) * 8;
    int a_kl  = (lane >> 4) * 16;
    uint32_t xr_a = (uint32_t)((a_row & 7) << 4);
    uint32_t a_off[4];
    #pragma unroll
    for (int i = 0; i < 4; i++) a_off[i] = (uint32_t)((a_row + i * 16) * 128);

    int b_row = wn * 32 + (lane & 7) + ((lane >> 4) << 3);
    int b_kl  = ((lane >> 3) & 1) * 16;
    uint32_t xr_b = (uint32_t)((b_row & 7) << 4);
    uint32_t b_off[2];
    #pragma unroll
    for (int p = 0; p < 2; p++) b_off[p] = (uint32_t)((b_row + p * 16) * 128);

    float acc[4][4][4];
    #pragma unroll
    for (int i = 0; i < 4; i++)
        #pragma unroll
        for (int j = 0; j < 4; j++)
            #pragma unroll
            for (int e = 0; e < 4; e++) acc[i][j][e] = 0.f;

    const int nch = 8;                         // K = 512

    auto load_stage = [&](int stg, int c) {
        uint32_t as = sb + (uint32_t)stg * STG;
        uint32_t bs = as + 16384;
        const __nv_bfloat16* ga = Ab + c * 64;
        const __nv_bfloat16* gb = Bb + c * 64;
        #pragma unroll
        for (int t = 0; t < 4; t++) {
            int sidx = t * 256 + tid;
            int m = sidx >> 3, cc = sidx & 7;
            uint32_t off = (uint32_t)(m * 128) + ((uint32_t)(cc * 16) ^ ((uint32_t)(m & 7) << 4));
            cp_async16(as + off, ga + (size_t)m * CH + cc * 8);
            cp_async16(bs + off, gb + (size_t)m * CH + cc * 8);
        }
    };

    load_stage(0, 0); CP_COMMIT();
    load_stage(1, 1); CP_COMMIT();

    for (int c = 0; c < nch; c++) {
        if (c + 2 < nch) { load_stage((c + 2) % 3, c + 2); CP_COMMIT(); }
        int remaining = nch - 1 - c;
        if (remaining >= 2)      { CP_WAIT(2); }
        else if (remaining == 1) { CP_WAIT(1); }
        else                     { CP_WAIT(0); }
        __syncthreads();

        uint32_t As = sb + (uint32_t)(c % 3) * STG;
        uint32_t Bs = As + 16384;
        #pragma unroll
        for (int k0 = 0; k0 < 64; k0 += 16) {
            uint32_t a[4][4], bfr[2][4];
            #pragma unroll
            for (int i = 0; i < 4; i++)
                ldsm4(a[i], As + a_off[i] + ((uint32_t)(k0 * 2 + a_kl) ^ xr_a));
            #pragma unroll
            for (int p = 0; p < 2; p++)
                ldsm4(bfr[p], Bs + b_off[p] + ((uint32_t)(k0 * 2 + b_kl) ^ xr_b));
            #pragma unroll
            for (int i = 0; i < 4; i++)
                #pragma unroll
                for (int j = 0; j < 4; j++)
                    mma16816(acc[i][j], a[i], bfr[j >> 1][(j & 1) * 2], bfr[j >> 1][(j & 1) * 2 + 1]);
        }
        __syncthreads();
    }

    // ---- epilogue: bias add (col for q/k, row for v), bf16 stores ----
    int r0 = lane >> 2, cq = (lane & 3) * 2;
    #pragma unroll
    for (int i = 0; i < 4; i++) {
        int rowg0 = m0 + wm * 64 + i * 16 + r0;
        float bu = 0.f, bl = 0.f;
        if (is_v) { bu = bias[rowg0]; bl = bias[rowg0 + 8]; }
        #pragma unroll
        for (int j = 0; j < 4; j++) {
            int colg = n0 + wn * 32 + j * 8 + cq;
            float v0 = acc[i][j][0], v1 = acc[i][j][1];
            float v2 = acc[i][j][2], v3 = acc[i][j][3];
            if (!is_v) {
                float b0 = bias[colg], b1 = bias[colg + 1];
                v0 += b0; v1 += b1; v2 += b0; v3 += b1;
            } else {
                v0 += bu; v1 += bu; v2 += bl; v3 += bl;
            }
            size_t o0 = (size_t)rowg0 * ldC + colg;
            size_t o1 = o0 + (size_t)8 * ldC;
            __nv_bfloat162 p0 = __floats2bfloat162_rn(v0, v1);
            __nv_bfloat162 p1 = __floats2bfloat162_rn(v2, v3);
            *(__nv_bfloat162*)(Cb + o0) = p0;
            *(__nv_bfloat162*)(Cb + o1) = p1;
        }
    }
}

// ---------------------------------------------------------------------------
// BF16 GEMM (best measured config): D[MxN] = sum_k A[m,k]*B[n,k], K-major,
// CTA 128x128, BK=64, 3-stage cp.async, 8 warps 2x4 (warp 64x32), 2 CTAs/SM
// (125 regs — DO NOT grow registers; R5 showed 1-CTA/SM collapse).
// EPI: 3 = fp32  x + acc + bias[row]            (proj + residual)
//      4 = bf16  exp(acc*scale), rowsum atomics (S / softmax numerator)
//      5 = bf16  acc * (1/rowsum[row])          (PV / softmax denominator)
// ---------------------------------------------------------------------------
template<int EPI>
__global__ void __launch_bounds__(256, 2) tc_gemm(
    const __nv_bfloat16* __restrict__ A, unsigned long long sA, int ldA,
    const __nv_bfloat16* __restrict__ B, unsigned long long sB, int ldB,
    void* __restrict__ C, unsigned long long sC, int ldC,
    const float* __restrict__ bias, float scale,
    const float* __restrict__ Xres, int K)
{
    extern __shared__ char dsm[];
    uint32_t sb = smem_u32(dsm);
    const uint32_t STG = 32768;
    int tid = threadIdx.x, wid = tid >> 5, lane = tid & 31;
    int wm = wid >> 2, wn = wid & 3;

    const __nv_bfloat16* Ab = A + (size_t)blockIdx.z * sA + (size_t)blockIdx.y * 128 * ldA;
    const __nv_bfloat16* Bb = B + (size_t)blockIdx.z * sB + (size_t)blockIdx.x * 128 * ldB;

    int a_row = wm * 64 + (lane & 7) + ((lane >> 3) & 1) * 8;
    int a_kl  = (lane >> 4) * 16;
    uint32_t xr_a = (uint32_t)((a_row & 7) << 4);
    uint32_t a_off[4];
    #pragma unroll
    for (int i = 0; i < 4; i++) a_off[i] = (uint32_t)((a_row + i * 16) * 128);

    int b_row = wn * 32 + (lane & 7) + ((lane >> 4) << 3);
    int b_kl  = ((lane >> 3) & 1) * 16;
    uint32_t xr_b = (uint32_t)((b_row & 7) << 4);
    uint32_t b_off[2];
    #pragma unroll
    for (int p = 0; p < 2; p++) b_off[p] = (uint32_t)((b_row + p * 16) * 128);

    float acc[4][4][4];
    #pragma unroll
    for (int i = 0; i < 4; i++)
        #pragma unroll
        for (int j = 0; j < 4; j++)
            #pragma unroll
            for (int e = 0; e < 4; e++) acc[i][j][e] = 0.f;

    int nch = K >> 6;

    auto load_stage = [&](int stg, int c) {
        uint32_t as = sb + (uint32_t)stg * STG;
        uint32_t bs = as + 16384;
        const __nv_bfloat16* ga = Ab + c * 64;
        const __nv_bfloat16* gb = Bb + c * 64;
        #pragma unroll
        for (int t = 0; t < 4; t++) {
            int sidx = t * 256 + tid;
            int m = sidx >> 3, cc = sidx & 7;
            uint32_t off = (uint32_t)(m * 128) + ((uint32_t)(cc * 16) ^ ((uint32_t)(m & 7) << 4));
            cp_async16(as + off, ga + (size_t)m * ldA + cc * 8);
            cp_async16(bs + off, gb + (size_t)m * ldB + cc * 8);
        }
    };

    if (0 < nch) { load_stage(0, 0); CP_COMMIT(); }
    if (1 < nch) { load_stage(1, 1); CP_COMMIT(); }

    for (int c = 0; c < nch; c++) {
        if (c + 2 < nch) { load_stage((c + 2) % 3, c + 2); CP_COMMIT(); }
        int remaining = nch - 1 - c;
        if (remaining >= 2)      { CP_WAIT(2); }
        else if (remaining == 1) { CP_WAIT(1); }
        else                     { CP_WAIT(0); }
        __syncthreads();

        uint32_t As = sb + (uint32_t)(c % 3) * STG;
        uint32_t Bs = As + 16384;
        #pragma unroll
        for (int k0 = 0; k0 < 64; k0 += 16) {
            uint32_t a[4][4], b[2][4];
            #pragma unroll
            for (int i = 0; i < 4; i++)
                ldsm4(a[i], As + a_off[i] + ((uint32_t)(k0 * 2 + a_kl) ^ xr_a));
            #pragma unroll
            for (int p = 0; p < 2; p++)
                ldsm4(b[p], Bs + b_off[p] + ((uint32_t)(k0 * 2 + b_kl) ^ xr_b));
            #pragma unroll
            for (int i = 0; i < 4; i++)
                #pragma unroll
                for (int j = 0; j < 4; j++)
                    mma16816(acc[i][j], a[i], b[j >> 1][(j & 1) * 2], b[j >> 1][(j & 1) * 2 + 1]);
        }
        __syncthreads();
    }

    // ---- epilogue: direct global stores ----
    int r0 = lane >> 2, cq = (lane & 3) * 2;
    #pragma unroll
    for (int i = 0; i < 4; i++) {
        int rowg0 = blockIdx.y * 128 + wm * 64 + i * 16 + r0;
        float inv_lo = 0.f, inv_hi = 0.f;
        if (EPI == 5) {
            const float* rsum = g_rowsum + (size_t)blockIdx.z * NPIX;
            inv_lo = 1.f / rsum[rowg0];
            inv_hi = 1.f / rsum[rowg0 + 8];
        }
        float p_lo = 0.f, p_hi = 0.f;
        #pragma unroll
        for (int j = 0; j < 4; j++) {
            int colg = blockIdx.x * 128 + wn * 32 + j * 8 + cq;
            float v0 = acc[i][j][0], v1 = acc[i][j][1];
            float v2 = acc[i][j][2], v3 = acc[i][j][3];
            if (EPI == 3) {
                float bu = bias[rowg0], bl = bias[rowg0 + 8];
                v0 += bu; v1 += bu; v2 += bl; v3 += bl;
            } else if (EPI == 4) {
                v0 = __expf(v0 * scale); v1 = __expf(v1 * scale);
                v2 = __expf(v2 * scale); v3 = __expf(v3 * scale);
                p_lo += v0 + v1; p_hi += v2 + v3;
            } else if (EPI == 5) {
                v0 *= inv_lo; v1 *= inv_lo;
                v2 *= inv_hi; v3 *= inv_hi;
            }
            size_t o0 = (size_t)blockIdx.z * sC + (size_t)rowg0 * ldC + colg;
            size_t o1 = o0 + (size_t)8 * ldC;
            if (EPI == 3) {
                const float* Xr0 = Xres + o0;
                const float* Xr1 = Xres + o1;
                float2 f0; f0.x = Xr0[0] + v0; f0.y = Xr0[1] + v1;
                float2 f1; f1.x = Xr1[0] + v2; f1.y = Xr1[1] + v3;
                *(float2*)((float*)C + o0) = f0;
                *(float2*)((float*)C + o1) = f1;
            } else {
                __nv_bfloat162 q0 = __floats2bfloat162_rn(v0, v1);
                __nv_bfloat162 q1 = __floats2bfloat162_rn(v2, v3);
                *(__nv_bfloat162*)((__nv_bfloat16*)C + o0) = q0;
                *(__nv_bfloat162*)((__nv_bfloat16*)C + o1) = q1;
            }
        }
        if (EPI == 4) {
            p_lo += __shfl_xor_sync(0xffffffffu, p_lo, 1);
            p_lo += __shfl_xor_sync(0xffffffffu, p_lo, 2);
            p_hi += __shfl_xor_sync(0xffffffffu, p_hi, 1);
            p_hi += __shfl_xor_sync(0xffffffffu, p_hi, 2);
            if ((lane & 3) == 0) {
                float* rsum = g_rowsum + (size_t)blockIdx.z * NPIX;
                atomicAdd(rsum + rowg0, p_lo);
                atomicAdd(rsum + rowg0 + 8, p_hi);
            }
        }
    }
}

// ---------------------------------------------------------------------------
extern "C" void kernel_launch(void* const* d_in, const int* in_sizes, int n_in,
                              void* d_out, int out_size) {
    (void)in_sizes; (void)n_in; (void)out_size;
    const float* x    = (const float*)d_in[0];
    const float* gn_w = (const float*)d_in[1];
    const float* gn_b = (const float*)d_in[2];
    const float* q_w  = (const float*)d_in[3];
    const float* q_b  = (const float*)d_in[4];
    const float* k_w  = (const float*)d_in[5];
    const float* k_b  = (const float*)d_in[6];
    const float* v_w  = (const float*)d_in[7];
    const float* v_b  = (const float*)d_in[8];
    const float* p_w  = (const float*)d_in[9];
    const float* p_b  = (const float*)d_in[10];
    float* out = (float*)d_out;

    const float qscale = 0.044194173824159216f;  // 512^-0.5 (applied inside exp)
    const int SMEM = 98304;                      // 3 stages x 32KB
    static bool attr_done = false;
    if (!attr_done) {
        cudaFuncSetAttribute(qkv_gemm,   cudaFuncAttributeMaxDynamicSharedMemorySize, SMEM);
        cudaFuncSetAttribute(tc_gemm<3>, cudaFuncAttributeMaxDynamicSharedMemorySize, SMEM);
        cudaFuncSetAttribute(tc_gemm<4>, cudaFuncAttributeMaxDynamicSharedMemorySize, SMEM);
        cudaFuncSetAttribute(tc_gemm<5>, cudaFuncAttributeMaxDynamicSharedMemorySize, SMEM);
        attr_done = true;
    }

    __nv_bfloat16 *qt, *kt, *vv, *ot, *Sp, *wp;
    cudaGetSymbolAddress((void**)&qt, g_qt);
    cudaGetSymbolAddress((void**)&kt, g_kt);
    cudaGetSymbolAddress((void**)&vv, g_v);
    cudaGetSymbolAddress((void**)&ot, g_ot);
    cudaGetSymbolAddress((void**)&Sp, g_S);
    cudaGetSymbolAddress((void**)&wp, g_wp);

    const unsigned long long sNC = (unsigned long long)NPIX * CH;    // 2097152
    const unsigned long long sNN = (unsigned long long)NPIX * NPIX;  // 16777216

    // GN (+ folded weight conversion + rowsum zero)
    gn_kernel<<<BATCH * 32, 1024>>>(x, gn_w, gn_b, q_w, k_w, v_w, p_w);

    // q, k, v convs in ONE launch: grid (4, 32, 24), z = {q:0-7, k:8-15, v:16-23}
    qkv_gemm<<<dim3(4, 32, 24), 256, SMEM>>>(q_b, k_b, v_b);

    // expS[i][j] = exp(qscale * q.k) : M=4096, N=4096, K=512
    tc_gemm<4><<<dim3(32, 32, BATCH), 256, SMEM>>>(qt, sNC, CH, kt, sNC, CH,
                                                   Sp, sNN, NPIX, nullptr, qscale, nullptr, CH);
    // o_t[i][c] = (expS . v^T) / rowsum[i] : M=4096, N=512, K=4096
    tc_gemm<5><<<dim3(4, 32, BATCH), 256, SMEM>>>(Sp, sNN, NPIX, vv, sNC, NPIX,
                                                  ot, sNC, CH, nullptr, 1.0f, nullptr, NPIX);
    // out[d][n] = x + Wp . o_t^T + pb : M=512, N=4096, K=512 (fp32 out)
    // grid.x MUST be 32 (N=4096 / 128-wide tiles; R6 bug was 16 -> half unwritten).
    tc_gemm<3><<<dim3(32, 4, BATCH), 256, SMEM>>>(wp, 0ull, CH, ot, sNC, CH,
                                                  out, sNC, NPIX, p_b, 1.0f, x, CH);
}

// round 15
// speedup vs baseline: 1.5425x; 1.5425x over previous
#include <cuda_runtime.h>
#include <cuda_bf16.h>
#include <cstdint>

#define BATCH 8
#define CH    512
#define NPIX  4096
#define EPS   1e-6f

// ---------------------------------------------------------------------------
// Scratch (__device__ globals: allocation-free per harness rules)
// ---------------------------------------------------------------------------
__device__ __nv_bfloat16 g_ht[BATCH * NPIX * CH];   // h^T [b][n][c]
__device__ __nv_bfloat16 g_qt[BATCH * NPIX * CH];   // q^T [b][n][d] (unscaled)
__device__ __nv_bfloat16 g_kt[BATCH * NPIX * CH];   // k^T [b][n][d]
__device__ __nv_bfloat16 g_v [BATCH * CH * NPIX];   // v   [b][d][n]
__device__ __nv_bfloat16 g_ot[BATCH * NPIX * CH];   // o^T [b][n][c]
__device__ __nv_bfloat16 g_S [134217728];           // [b][i][j] exp(logits)
__device__ float         g_rowsum[BATCH * NPIX];    // softmax denominators
__device__ __nv_bfloat16 g_wq[CH * CH], g_wk[CH * CH], g_wv[CH * CH], g_wp[CH * CH];

// ---------------------------------------------------------------------------
// PTX helpers (base-arch features only: PTX target is sm_103 w/o 'a' suffix)
// ---------------------------------------------------------------------------
__device__ __forceinline__ uint32_t smem_u32(const void* p) {
    uint32_t a;
    asm("{ .reg .u64 t; cvta.to.shared.u64 t, %1; cvt.u32.u64 %0, t; }"
        : "=r"(a) : "l"(p));
    return a;
}
__device__ __forceinline__ void cp_async16(uint32_t saddr, const void* gptr) {
    asm volatile("cp.async.cg.shared.global [%0], [%1], 16;\n"
                 :: "r"(saddr), "l"(gptr));
}
#define CP_COMMIT() asm volatile("cp.async.commit_group;\n" ::: "memory")
#define CP_WAIT(N)  asm volatile("cp.async.wait_group %0;\n" :: "n"(N) : "memory")

__device__ __forceinline__ void ldsm4(uint32_t* r, uint32_t addr) {
    asm volatile("ldmatrix.sync.aligned.m8n8.x4.shared.b16 {%0,%1,%2,%3}, [%4];"
                 : "=r"(r[0]), "=r"(r[1]), "=r"(r[2]), "=r"(r[3]) : "r"(addr));
}
__device__ __forceinline__ void mma16816(float* c, const uint32_t* a,
                                         uint32_t b0, uint32_t b1) {
    asm volatile("mma.sync.aligned.m16n8k16.row.col.f32.bf16.bf16.f32 "
                 "{%0,%1,%2,%3}, {%4,%5,%6,%7}, {%8,%9}, {%0,%1,%2,%3};"
                 : "+f"(c[0]), "+f"(c[1]), "+f"(c[2]), "+f"(c[3])
                 : "r"(a[0]), "r"(a[1]), "r"(a[2]), "r"(a[3]), "r"(b0), "r"(b1));
}

// ---------------------------------------------------------------------------
// GroupNorm -> bf16 h^T[b][n][c]; ALSO folds in weight fp32->bf16 conversion
// (one float4 per thread: 256 blocks x 1024 thr == 262144 units) and
// g_rowsum zeroing, eliminating the separate wconv launch.
// ---------------------------------------------------------------------------
__global__ __launch_bounds__(1024) void gn_kernel(const float* __restrict__ x,
                                                  const float* __restrict__ w,
                                                  const float* __restrict__ bgn,
                                                  const float* __restrict__ qw,
                                                  const float* __restrict__ kw,
                                                  const float* __restrict__ vw,
                                                  const float* __restrict__ pw) {
    int bg = blockIdx.x;                       // b*32 + g
    int tid = threadIdx.x;

    // ---- folded weight conversion + rowsum zero (independent work) ----
    {
        int i4 = bg * 1024 + tid;              // 0..262143 float4 units
        if (i4 < BATCH * NPIX) g_rowsum[i4] = 0.f;
        const float* src = (i4 < 65536) ? qw : (i4 < 131072) ? kw
                          : (i4 < 196608) ? vw : pw;
        __nv_bfloat16* dst = (i4 < 65536) ? g_wq : (i4 < 131072) ? g_wk
                            : (i4 < 196608) ? g_wv : g_wp;
        int off = i4 & 65535;
        float4 vv = ((const float4*)src)[off];
        __nv_bfloat162 lo = __floats2bfloat162_rn(vv.x, vv.y);
        __nv_bfloat162 hi = __floats2bfloat162_rn(vv.z, vv.w);
        uint2 u; u.x = *(uint32_t*)&lo; u.y = *(uint32_t*)&hi;
        ((uint2*)dst)[off] = u;
    }

    // ---- GroupNorm proper ----
    size_t base = (size_t)bg * (16 * NPIX);
    const float4* x4 = (const float4*)(x + base);

    float s = 0.f, ss = 0.f;
    #pragma unroll
    for (int t = 0; t < 16; t++) {
        float4 v = x4[tid + t * 1024];
        s  += v.x + v.y + v.z + v.w;
        ss += v.x * v.x + v.y * v.y + v.z * v.z + v.w * v.w;
    }
    __shared__ float rs[32], rss[32];
    __shared__ float sc_s[16], off_s[16];
    #pragma unroll
    for (int o = 16; o; o >>= 1) {
        s  += __shfl_xor_sync(0xffffffffu, s, o);
        ss += __shfl_xor_sync(0xffffffffu, ss, o);
    }
    if ((tid & 31) == 0) { rs[tid >> 5] = s; rss[tid >> 5] = ss; }
    __syncthreads();
    if (tid < 32) {
        s = rs[tid]; ss = rss[tid];
        #pragma unroll
        for (int o = 16; o; o >>= 1) {
            s  += __shfl_xor_sync(0xffffffffu, s, o);
            ss += __shfl_xor_sync(0xffffffffu, ss, o);
        }
        if (tid == 0) {
            float mean = s * (1.f / 65536.f);
            float var  = ss * (1.f / 65536.f) - mean * mean;
            rs[0] = mean; rss[0] = rsqrtf(var + EPS);
        }
    }
    __syncthreads();
    int b = bg >> 5, g = bg & 31, c0 = g * 16;
    if (tid < 16) {
        float mean = rs[0], inv = rss[0];
        float scv = w[c0 + tid] * inv;
        sc_s[tid]  = scv;
        off_s[tid] = bgn[c0 + tid] - mean * scv;
    }
    __syncthreads();

    #pragma unroll
    for (int nb = 0; nb < 4; nb++) {
        int n = nb * 1024 + tid;
        __nv_bfloat16 hv[16];
        #pragma unroll
        for (int cc = 0; cc < 16; cc++) {
            float xv = x[base + (size_t)cc * NPIX + n];
            hv[cc] = __float2bfloat16(xv * sc_s[cc] + off_s[cc]);
        }
        uint4* dst = (uint4*)(g_ht + ((size_t)b * NPIX + n) * CH + c0);
        uint4* src = (uint4*)hv;
        dst[0] = src[0];
        dst[1] = src[1];
    }
}

// ---------------------------------------------------------------------------
// Merged q/k/v conv GEMM, one launch. grid (4, 32, 24):
//   z in [0,8)   : q^T[n][d] = h^T . Wq^T + qb   (m0 from y, n0 from x, bias[col])
//   z in [8,16)  : k^T[n][d] = h^T . Wk^T + kb   (same shape)
//   z in [16,24) : v[d][n]   = Wv . h^T^T + vb   (m0 from x, n0 from y, bias[row])
// Same mainloop as tc_gemm, K=512 fixed (8 chunks). All selection is uniform.
// ---------------------------------------------------------------------------
__global__ void __launch_bounds__(256, 2) qkv_gemm(
    const float* __restrict__ q_b, const float* __restrict__ k_b,
    const float* __restrict__ v_b)
{
    extern __shared__ char dsm[];
    uint32_t sb = smem_u32(dsm);
    const uint32_t STG = 32768;
    int tid = threadIdx.x, wid = tid >> 5, lane = tid & 31;
    int wm = wid >> 2, wn = wid & 3;

    const unsigned long long sNC = (unsigned long long)NPIX * CH;

    int z = blockIdx.z;
    int b = z & 7;
    bool is_v = (z >= 16);
    int m0, n0, ldC;
    const __nv_bfloat16 *Ab, *Bb;
    __nv_bfloat16* Cb;
    const float* bias;
    if (!is_v) {
        bool is_q = (z < 8);
        m0 = blockIdx.y * 128;                 // n tiles (4096)
        n0 = blockIdx.x * 128;                 // d tiles (512)
        Ab = g_ht + (size_t)b * sNC + (size_t)m0 * CH;
        Bb = (is_q ? g_wq : g_wk) + (size_t)n0 * CH;
        Cb = (is_q ? g_qt : g_kt) + (size_t)b * sNC;
        bias = is_q ? q_b : k_b;
        ldC = CH;
    } else {
        m0 = blockIdx.x * 128;                 // d tiles (512)
        n0 = blockIdx.y * 128;                 // n tiles (4096)
        Ab = g_wv + (size_t)m0 * CH;
        Bb = g_ht + (size_t)b * sNC + (size_t)n0 * CH;
        Cb = g_v + (size_t)b * sNC;
        bias = v_b;
        ldC = NPIX;
    }

    int a_row = wm * 64 + (lane & 7) + ((lane >> 3) & 1) * 8;
    int a_kl  = (lane >> 4) * 16;
    uint32_t xr_a = (uint32_t)((a_row & 7) << 4);
    uint32_t a_off[4];
    #pragma unroll
    for (int i = 0; i < 4; i++) a_off[i] = (uint32_t)((a_row + i * 16) * 128);

    int b_row = wn * 32 + (lane & 7) + ((lane >> 4) << 3);
    int b_kl  = ((lane >> 3) & 1) * 16;
    uint32_t xr_b = (uint32_t)((b_row & 7) << 4);
    uint32_t b_off[2];
    #pragma unroll
    for (int p = 0; p < 2; p++) b_off[p] = (uint32_t)((b_row + p * 16) * 128);

    float acc[4][4][4];
    #pragma unroll
    for (int i = 0; i < 4; i++)
        #pragma unroll
        for (int j = 0; j < 4; j++)
            #pragma unroll
            for (int e = 0; e < 4; e++) acc[i][j][e] = 0.f;

    const int nch = 8;                         // K = 512

    auto load_stage = [&](int stg, int c) {
        uint32_t as = sb + (uint32_t)stg * STG;
        uint32_t bs = as + 16384;
        const __nv_bfloat16* ga = Ab + c * 64;
        const __nv_bfloat16* gb = Bb + c * 64;
        #pragma unroll
        for (int t = 0; t < 4; t++) {
            int sidx = t * 256 + tid;
            int m = sidx >> 3, cc = sidx & 7;
            uint32_t off = (uint32_t)(m * 128) + ((uint32_t)(cc * 16) ^ ((uint32_t)(m & 7) << 4));
            cp_async16(as + off, ga + (size_t)m * CH + cc * 8);
            cp_async16(bs + off, gb + (size_t)m * CH + cc * 8);
        }
    };

    load_stage(0, 0); CP_COMMIT();
    load_stage(1, 1); CP_COMMIT();

    for (int c = 0; c < nch; c++) {
        if (c + 2 < nch) { load_stage((c + 2) % 3, c + 2); CP_COMMIT(); }
        int remaining = nch - 1 - c;
        if (remaining >= 2)      { CP_WAIT(2); }
        else if (remaining == 1) { CP_WAIT(1); }
        else                     { CP_WAIT(0); }
        __syncthreads();

        uint32_t As = sb + (uint32_t)(c % 3) * STG;
        uint32_t Bs = As + 16384;
        #pragma unroll
        for (int k0 = 0; k0 < 64; k0 += 16) {
            uint32_t a[4][4], bfr[2][4];
            #pragma unroll
            for (int i = 0; i < 4; i++)
                ldsm4(a[i], As + a_off[i] + ((uint32_t)(k0 * 2 + a_kl) ^ xr_a));
            #pragma unroll
            for (int p = 0; p < 2; p++)
                ldsm4(bfr[p], Bs + b_off[p] + ((uint32_t)(k0 * 2 + b_kl) ^ xr_b));
            #pragma unroll
            for (int i = 0; i < 4; i++)
                #pragma unroll
                for (int j = 0; j < 4; j++)
                    mma16816(acc[i][j], a[i], bfr[j >> 1][(j & 1) * 2], bfr[j >> 1][(j & 1) * 2 + 1]);
        }
        __syncthreads();
    }

    // ---- epilogue: bias add (col for q/k, row for v), bf16 stores ----
    int r0 = lane >> 2, cq = (lane & 3) * 2;
    #pragma unroll
    for (int i = 0; i < 4; i++) {
        int rowg0 = m0 + wm * 64 + i * 16 + r0;
        float bu = 0.f, bl = 0.f;
        if (is_v) { bu = bias[rowg0]; bl = bias[rowg0 + 8]; }
        #pragma unroll
        for (int j = 0; j < 4; j++) {
            int colg = n0 + wn * 32 + j * 8 + cq;
            float v0 = acc[i][j][0], v1 = acc[i][j][1];
            float v2 = acc[i][j][2], v3 = acc[i][j][3];
            if (!is_v) {
                float b0 = bias[colg], b1 = bias[colg + 1];
                v0 += b0; v1 += b1; v2 += b0; v3 += b1;
            } else {
                v0 += bu; v1 += bu; v2 += bl; v3 += bl;
            }
            size_t o0 = (size_t)rowg0 * ldC + colg;
            size_t o1 = o0 + (size_t)8 * ldC;
            __nv_bfloat162 p0 = __floats2bfloat162_rn(v0, v1);
            __nv_bfloat162 p1 = __floats2bfloat162_rn(v2, v3);
            *(__nv_bfloat162*)(Cb + o0) = p0;
            *(__nv_bfloat162*)(Cb + o1) = p1;
        }
    }
}

// ---------------------------------------------------------------------------
// BF16 GEMM (best measured config): D[MxN] = sum_k A[m,k]*B[n,k], K-major,
// CTA 128x128, BK=64, 3-stage cp.async, 8 warps 2x4 (warp 64x32), 2 CTAs/SM
// (125 regs — DO NOT grow registers; R5 showed 1-CTA/SM collapse).
// EPI: 3 = fp32  x + acc + bias[row]            (proj + residual)
//      4 = bf16  exp(acc*scale), rowsum atomics (S / softmax numerator)
//      5 = bf16  acc * (1/rowsum[row])          (PV / softmax denominator)
// ---------------------------------------------------------------------------
template<int EPI>
__global__ void __launch_bounds__(256, 2) tc_gemm(
    const __nv_bfloat16* __restrict__ A, unsigned long long sA, int ldA,
    const __nv_bfloat16* __restrict__ B, unsigned long long sB, int ldB,
    void* __restrict__ C, unsigned long long sC, int ldC,
    const float* __restrict__ bias, float scale,
    const float* __restrict__ Xres, int K)
{
    extern __shared__ char dsm[];
    uint32_t sb = smem_u32(dsm);
    const uint32_t STG = 32768;
    int tid = threadIdx.x, wid = tid >> 5, lane = tid & 31;
    int wm = wid >> 2, wn = wid & 3;

    const __nv_bfloat16* Ab = A + (size_t)blockIdx.z * sA + (size_t)blockIdx.y * 128 * ldA;
    const __nv_bfloat16* Bb = B + (size_t)blockIdx.z * sB + (size_t)blockIdx.x * 128 * ldB;

    int a_row = wm * 64 + (lane & 7) + ((lane >> 3) & 1) * 8;
    int a_kl  = (lane >> 4) * 16;
    uint32_t xr_a = (uint32_t)((a_row & 7) << 4);
    uint32_t a_off[4];
    #pragma unroll
    for (int i = 0; i < 4; i++) a_off[i] = (uint32_t)((a_row + i * 16) * 128);

    int b_row = wn * 32 + (lane & 7) + ((lane >> 4) << 3);
    int b_kl  = ((lane >> 3) & 1) * 16;
    uint32_t xr_b = (uint32_t)((b_row & 7) << 4);
    uint32_t b_off[2];
    #pragma unroll
    for (int p = 0; p < 2; p++) b_off[p] = (uint32_t)((b_row + p * 16) * 128);

    float acc[4][4][4];
    #pragma unroll
    for (int i = 0; i < 4; i++)
        #pragma unroll
        for (int j = 0; j < 4; j++)
            #pragma unroll
            for (int e = 0; e < 4; e++) acc[i][j][e] = 0.f;

    int nch = K >> 6;

    auto load_stage = [&](int stg, int c) {
        uint32_t as = sb + (uint32_t)stg * STG;
        uint32_t bs = as + 16384;
        const __nv_bfloat16* ga = Ab + c * 64;
        const __nv_bfloat16* gb = Bb + c * 64;
        #pragma unroll
        for (int t = 0; t < 4; t++) {
            int sidx = t * 256 + tid;
            int m = sidx >> 3, cc = sidx & 7;
            uint32_t off = (uint32_t)(m * 128) + ((uint32_t)(cc * 16) ^ ((uint32_t)(m & 7) << 4));
            cp_async16(as + off, ga + (size_t)m * ldA + cc * 8);
            cp_async16(bs + off, gb + (size_t)m * ldB + cc * 8);
        }
    };

    if (0 < nch) { load_stage(0, 0); CP_COMMIT(); }
    if (1 < nch) { load_stage(1, 1); CP_COMMIT(); }

    for (int c = 0; c < nch; c++) {
        if (c + 2 < nch) { load_stage((c + 2) % 3, c + 2); CP_COMMIT(); }
        int remaining = nch - 1 - c;
        if (remaining >= 2)      { CP_WAIT(2); }
        else if (remaining == 1) { CP_WAIT(1); }
        else                     { CP_WAIT(0); }
        __syncthreads();

        uint32_t As = sb + (uint32_t)(c % 3) * STG;
        uint32_t Bs = As + 16384;
        #pragma unroll
        for (int k0 = 0; k0 < 64; k0 += 16) {
            uint32_t a[4][4], b[2][4];
            #pragma unroll
            for (int i = 0; i < 4; i++)
                ldsm4(a[i], As + a_off[i] + ((uint32_t)(k0 * 2 + a_kl) ^ xr_a));
            #pragma unroll
            for (int p = 0; p < 2; p++)
                ldsm4(b[p], Bs + b_off[p] + ((uint32_t)(k0 * 2 + b_kl) ^ xr_b));
            #pragma unroll
            for (int i = 0; i < 4; i++)
                #pragma unroll
                for (int j = 0; j < 4; j++)
                    mma16816(acc[i][j], a[i], b[j >> 1][(j & 1) * 2], b[j >> 1][(j & 1) * 2 + 1]);
        }
        __syncthreads();
    }

    // ---- epilogue: direct global stores ----
    int r0 = lane >> 2, cq = (lane & 3) * 2;
    #pragma unroll
    for (int i = 0; i < 4; i++) {
        int rowg0 = blockIdx.y * 128 + wm * 64 + i * 16 + r0;
        float inv_lo = 0.f, inv_hi = 0.f;
        if (EPI == 5) {
            const float* rsum = g_rowsum + (size_t)blockIdx.z * NPIX;
            inv_lo = 1.f / rsum[rowg0];
            inv_hi = 1.f / rsum[rowg0 + 8];
        }
        float p_lo = 0.f, p_hi = 0.f;
        #pragma unroll
        for (int j = 0; j < 4; j++) {
            int colg = blockIdx.x * 128 + wn * 32 + j * 8 + cq;
            float v0 = acc[i][j][0], v1 = acc[i][j][1];
            float v2 = acc[i][j][2], v3 = acc[i][j][3];
            if (EPI == 3) {
                float bu = bias[rowg0], bl = bias[rowg0 + 8];
                v0 += bu; v1 += bu; v2 += bl; v3 += bl;
            } else if (EPI == 4) {
                v0 = __expf(v0 * scale); v1 = __expf(v1 * scale);
                v2 = __expf(v2 * scale); v3 = __expf(v3 * scale);
                p_lo += v0 + v1; p_hi += v2 + v3;
            } else if (EPI == 5) {
                v0 *= inv_lo; v1 *= inv_lo;
                v2 *= inv_hi; v3 *= inv_hi;
            }
            size_t o0 = (size_t)blockIdx.z * sC + (size_t)rowg0 * ldC + colg;
            size_t o1 = o0 + (size_t)8 * ldC;
            if (EPI == 3) {
                const float* Xr0 = Xres + o0;
                const float* Xr1 = Xres + o1;
                float2 f0; f0.x = Xr0[0] + v0; f0.y = Xr0[1] + v1;
                float2 f1; f1.x = Xr1[0] + v2; f1.y = Xr1[1] + v3;
                *(float2*)((float*)C + o0) = f0;
                *(float2*)((float*)C + o1) = f1;
            } else {
                __nv_bfloat162 q0 = __floats2bfloat162_rn(v0, v1);
                __nv_bfloat162 q1 = __floats2bfloat162_rn(v2, v3);
                *(__nv_bfloat162*)((__nv_bfloat16*)C + o0) = q0;
                *(__nv_bfloat162*)((__nv_bfloat16*)C + o1) = q1;
            }
        }
        if (EPI == 4) {
            p_lo += __shfl_xor_sync(0xffffffffu, p_lo, 1);
            p_lo += __shfl_xor_sync(0xffffffffu, p_lo, 2);
            p_hi += __shfl_xor_sync(0xffffffffu, p_hi, 1);
            p_hi += __shfl_xor_sync(0xffffffffu, p_hi, 2);
            if ((lane & 3) == 0) {
                float* rsum = g_rowsum + (size_t)blockIdx.z * NPIX;
                atomicAdd(rsum + rowg0, p_lo);
                atomicAdd(rsum + rowg0 + 8, p_hi);
            }
        }
    }
}

// ---------------------------------------------------------------------------
extern "C" void kernel_launch(void* const* d_in, const int* in_sizes, int n_in,
                              void* d_out, int out_size) {
    (void)in_sizes; (void)n_in; (void)out_size;
    const float* x    = (const float*)d_in[0];
    const float* gn_w = (const float*)d_in[1];
    const float* gn_b = (const float*)d_in[2];
    const float* q_w  = (const float*)d_in[3];
    const float* q_b  = (const float*)d_in[4];
    const float* k_w  = (const float*)d_in[5];
    const float* k_b  = (const float*)d_in[6];
    const float* v_w  = (const float*)d_in[7];
    const float* v_b  = (const float*)d_in[8];
    const float* p_w  = (const float*)d_in[9];
    const float* p_b  = (const float*)d_in[10];
    float* out = (float*)d_out;

    const float qscale = 0.044194173824159216f;  // 512^-0.5 (applied inside exp)
    const int SMEM = 98304;                      // 3 stages x 32KB
    static bool attr_done = false;
    if (!attr_done) {
        cudaFuncSetAttribute(qkv_gemm,   cudaFuncAttributeMaxDynamicSharedMemorySize, SMEM);
        cudaFuncSetAttribute(tc_gemm<3>, cudaFuncAttributeMaxDynamicSharedMemorySize, SMEM);
        cudaFuncSetAttribute(tc_gemm<4>, cudaFuncAttributeMaxDynamicSharedMemorySize, SMEM);
        cudaFuncSetAttribute(tc_gemm<5>, cudaFuncAttributeMaxDynamicSharedMemorySize, SMEM);
        attr_done = true;
    }

    __nv_bfloat16 *qt, *kt, *vv, *ot, *Sp, *wp;
    cudaGetSymbolAddress((void**)&qt, g_qt);
    cudaGetSymbolAddress((void**)&kt, g_kt);
    cudaGetSymbolAddress((void**)&vv, g_v);
    cudaGetSymbolAddress((void**)&ot, g_ot);
    cudaGetSymbolAddress((void**)&Sp, g_S);
    cudaGetSymbolAddress((void**)&wp, g_wp);

    const unsigned long long sNC = (unsigned long long)NPIX * CH;    // 2097152
    const unsigned long long sNN = (unsigned long long)NPIX * NPIX;  // 16777216

    // GN (+ folded weight conversion + rowsum zero)
    gn_kernel<<<BATCH * 32, 1024>>>(x, gn_w, gn_b, q_w, k_w, v_w, p_w);

    // q, k, v convs in ONE launch: grid (4, 32, 24), z = {q:0-7, k:8-15, v:16-23}
    qkv_gemm<<<dim3(4, 32, 24), 256, SMEM>>>(q_b, k_b, v_b);

    // expS[i][j] = exp(qscale * q.k) : M=4096, N=4096, K=512
    tc_gemm<4><<<dim3(32, 32, BATCH), 256, SMEM>>>(qt, sNC, CH, kt, sNC, CH,
                                                   Sp, sNN, NPIX, nullptr, qscale, nullptr, CH);
    // o_t[i][c] = (expS . v^T) / rowsum[i] : M=4096, N=512, K=4096
    tc_gemm<5><<<dim3(4, 32, BATCH), 256, SMEM>>>(Sp, sNN, NPIX, vv, sNC, NPIX,
                                                  ot, sNC, CH, nullptr, 1.0f, nullptr, NPIX);
    // out[d][n] = x + Wp . o_t^T + pb : M=512, N=4096, K=512 (fp32 out)
    // grid.x MUST be 32 (N=4096 / 128-wide tiles; R6 bug was 16 -> half unwritten).
    tc_gemm<3><<<dim3(32, 4, BATCH), 256, SMEM>>>(wp, 0ull, CH, ot, sNC, CH,
                                                  out, sNC, NPIX, p_b, 1.0f, x, CH);
}